// round 17
// baseline (speedup 1.0000x reference)
#include <cuda_runtime.h>
#include <cstdint>

// Problem constants
#define Bb 512
#define Tt 512
#define Ff 32
#define Hh 128
#define Ll 5
#define G4 512          // total gate rows (4H)
#define ROWS 4          // batch rows per CTA
#define K2T 80          // (H+F)/2 total packed k-pairs (k2 0..63 = W_hh, 64..79 = W_ih)
#define K2Q 20          // k-pairs per k-quarter
#define KREG 17         // reg-resident k-pairs per register gate
#define KSM  3          // smem tail k-pairs per register gate (K2Q - KREG)
#define NTHREADS 512

// ---------------- smem layout ----------------
struct __align__(16) Smem {
    float2 wlo[4][K2Q][2][128];  // 163840 B: smem gates (g0+256, g0+384): [kq][kk][j][g0]
    float2 whi[4][KSM][2][128];  // 24576 B: reg-gates' tail k2 (g0, g0+128): [kq][kk-KREG][j][g0]
    float2 hx[K2T][ROWS];        // 2560 B: hx[k2][r]; k<128 -> h, k>=128 -> x_t
    float4 red[4][ROWS][128];    // 32768 B: packed (i,f,g,o) partials, slab d=(r-kq)&3; slab 0 unused
};
// total 223,744 B (dynamic smem; 232,448 B failed to launch — R13/R14 lesson)

// packed f32x2 FMA (Blackwell)
__device__ __forceinline__ unsigned long long ffma2(unsigned long long a,
                                                    unsigned long long b,
                                                    unsigned long long c) {
    unsigned long long d;
    asm("fma.rn.f32x2 %0, %1, %2, %3;" : "=l"(d) : "l"(a), "l"(b), "l"(c));
    return d;
}
__device__ __forceinline__ float hsum2(unsigned long long a) {
    float2 v = *reinterpret_cast<float2*>(&a);
    return v.x + v.y;
}
// HW tanh (MUFU.TANH): ~2e-4 abs err, single op — validated R15: final rel_err 3.7e-6
__device__ __forceinline__ float tanh_hw(float v) {
    float r;
    asm("tanh.approx.f32 %0, %1;" : "=f"(r) : "f"(v));
    return r;
}
__device__ __forceinline__ float sig_hw(float v) {
    return fmaf(tanh_hw(0.5f * v), 0.5f, 0.5f);
}
// select one of 4 statically-unrolled values by runtime index (2 SELs, no local mem)
__device__ __forceinline__ float pick4(float v0, float v1, float v2, float v3, int k) {
    float a = (k & 1) ? v1 : v0;
    float b = (k & 1) ? v3 : v2;
    return (k & 2) ? b : a;
}
// named barrier: id in [1,16), count must cover all participating threads
__device__ __forceinline__ void bar_named(int id, int cnt) {
    asm volatile("bar.sync %0, %1;" :: "r"(id), "r"(cnt) : "memory");
}

// ---------------- kernel ----------------
// 128 CTAs x 512 threads. CTA b owns batch rows [4b, 4b+4) and all 512 gate rows.
// Thread t: k-quarter kq = t>>7 (20 k2), gates {g0, g0+128, g0+256, g0+384},
// g0 = t&127. Gates g0, g0+128: 17 of 20 k2 in REGISTERS, 3 from smem; gates
// g0+256, g0+384: all from smem (conflict-free LDS.64). Per step:
//   GEMM 20 iters x (2 broadcast LDS.128 h + 2-4 LDS.64 w + 16 FFMA2);
//   foreign rows' (i,f,g,o) packed as ONE float4 STS each (3 STS.128) into slab
//   (r-kq)&3; own-row partials stay in REGISTERS;
//   NAMED BAR (group = same g0-block: warps {c,c+4,c+8,c+12}, 128 thr);
//   update (row kq, col g0) = own + 3x LDS.128 slabs + bias, HW tanh;
//   full __syncthreads (h-ready).
__global__ void __launch_bounds__(NTHREADS, 1)
lstm_kernel(const float* __restrict__ x,
            const float* __restrict__ W_ih,
            const float* __restrict__ W_hh,
            const float* __restrict__ b_ih,
            const float* __restrict__ b_hh,
            const float* __restrict__ W_fc,
            const float* __restrict__ b_fc,
            float* __restrict__ out)
{
    extern __shared__ unsigned char smem_raw[];
    Smem* s = reinterpret_cast<Smem*>(smem_raw);
    const int tid  = threadIdx.x;
    const int kq   = tid >> 7;          // k-quarter AND my update row
    const int g0   = tid & 127;         // base gate row AND my update column
    const int grp  = (tid >> 5) & 3;    // g0-block group for the named barrier
    const int row0 = blockIdx.x * ROWS;

    // ---- prologue: weights -> regs (g0,g0+128 first 17 k2) and smem ----
    const float2* whh2 = reinterpret_cast<const float2*>(W_hh);   // row g: 64 float2
    const float2* wih2 = reinterpret_cast<const float2*>(W_ih);   // row g: 16 float2
    unsigned long long Wr0[KREG], Wr1[KREG];
    {
        const int base = kq * K2Q;
        #pragma unroll
        for (int kk = 0; kk < K2Q; ++kk) {
            int k2 = base + kk;
            float2 v0 = (k2 < 64) ? __ldg(whh2 + (size_t)g0 * 64 + k2)
                                  : __ldg(wih2 + (size_t)g0 * 16 + (k2 - 64));
            float2 v1 = (k2 < 64) ? __ldg(whh2 + (size_t)(g0 + 128) * 64 + k2)
                                  : __ldg(wih2 + (size_t)(g0 + 128) * 16 + (k2 - 64));
            if (kk < KREG) {
                Wr0[kk] = *reinterpret_cast<unsigned long long*>(&v0);
                Wr1[kk] = *reinterpret_cast<unsigned long long*>(&v1);
            } else {
                s->whi[kq][kk - KREG][0][g0] = v0;
                s->whi[kq][kk - KREG][1][g0] = v1;
            }
            float2 v2 = (k2 < 64) ? __ldg(whh2 + (size_t)(g0 + 256) * 64 + k2)
                                  : __ldg(wih2 + (size_t)(g0 + 256) * 16 + (k2 - 64));
            s->wlo[kq][kk][0][g0] = v2;
            float2 v3 = (k2 < 64) ? __ldg(whh2 + (size_t)(g0 + 384) * 64 + k2)
                                  : __ldg(wih2 + (size_t)(g0 + 384) * 16 + (k2 - 64));
            s->wlo[kq][kk][1][g0] = v3;
        }
    }
    // bias for my 4 gates (added to the register-resident own partial)
    float cb[4];
    #pragma unroll
    for (int j = 0; j < 4; ++j)
        cb[j] = b_ih[g0 + 128 * j] + b_hh[g0 + 128 * j];

    // ---- init state: zero h region (k2 0..63), x(t=0) into k2 64..79 ----
    if (tid < 256) s->hx[tid >> 2][tid & 3] = make_float2(0.f, 0.f);
    const int xr = (tid >> 5) & 3, xf = tid & 31;          // x-loader role for tid<128
    const float* xptr = x + (size_t)(row0 + xr) * Tt * Ff + xf;
    if (tid < 128) {
        float v = __ldg(xptr);
        reinterpret_cast<float*>(&s->hx[64 + (xf >> 1)][xr])[xf & 1] = v;
    }
    __syncthreads();

    float c_ = 0.f;                     // cell state: row kq, col g0

    const unsigned long long* hq =
        reinterpret_cast<const unsigned long long*>(&s->hx[kq * K2Q][0]);
    const unsigned long long* wlo_p =
        reinterpret_cast<const unsigned long long*>(&s->wlo[kq][0][0][g0]);
    const unsigned long long* whi_p =
        reinterpret_cast<const unsigned long long*>(&s->whi[kq][0][0][g0]);

    for (int st = 0; st < Tt; ++st) {
        // prefetch next x slice (tid<128)
        float xnext = 0.f;
        if (tid < 128 && st + 1 < Tt) xnext = __ldg(xptr + (size_t)(st + 1) * Ff);

        // ---- GEMM: 4 gates x 4 batch rows, my k-quarter ----
        unsigned long long a0[ROWS], a1[ROWS], a2[ROWS], a3[ROWS];
        #pragma unroll
        for (int r = 0; r < ROWS; ++r) { a0[r] = 0ull; a1[r] = 0ull; a2[r] = 0ull; a3[r] = 0ull; }
        #pragma unroll
        for (int kk = 0; kk < K2Q; ++kk) {
            ulonglong2 hAB = *reinterpret_cast<const ulonglong2*>(hq + kk * 4);     // rows 0,1
            ulonglong2 hCD = *reinterpret_cast<const ulonglong2*>(hq + kk * 4 + 2); // rows 2,3
            unsigned long long w0 = (kk < KREG) ? Wr0[kk]
                                                : whi_p[(size_t)(kk - KREG) * 256];
            unsigned long long w1 = (kk < KREG) ? Wr1[kk]
                                                : whi_p[(size_t)(kk - KREG) * 256 + 128];
            unsigned long long w2 = wlo_p[(size_t)kk * 256];        // wlo[kq][kk][0][g0]
            unsigned long long w3 = wlo_p[(size_t)kk * 256 + 128];  // wlo[kq][kk][1][g0]
            a0[0] = ffma2(hAB.x, w0, a0[0]); a0[1] = ffma2(hAB.y, w0, a0[1]);
            a0[2] = ffma2(hCD.x, w0, a0[2]); a0[3] = ffma2(hCD.y, w0, a0[3]);
            a1[0] = ffma2(hAB.x, w1, a1[0]); a1[1] = ffma2(hAB.y, w1, a1[1]);
            a1[2] = ffma2(hCD.x, w1, a1[2]); a1[3] = ffma2(hCD.y, w1, a1[3]);
            a2[0] = ffma2(hAB.x, w2, a2[0]); a2[1] = ffma2(hAB.y, w2, a2[1]);
            a2[2] = ffma2(hCD.x, w2, a2[2]); a2[3] = ffma2(hCD.y, w2, a2[3]);
            a3[0] = ffma2(hAB.x, w3, a3[0]); a3[1] = ffma2(hAB.y, w3, a3[1]);
            a3[2] = ffma2(hCD.x, w3, a3[2]); a3[3] = ffma2(hCD.y, w3, a3[3]);
        }

        // horizontal sums
        float s0[ROWS], s1[ROWS], s2[ROWS], s3[ROWS];
        #pragma unroll
        for (int r = 0; r < ROWS; ++r) {
            s0[r] = hsum2(a0[r]); s1[r] = hsum2(a1[r]);
            s2[r] = hsum2(a2[r]); s3[r] = hsum2(a3[r]);
        }
        // own-row partials stay in registers (row kq)
        float own0 = pick4(s0[0], s0[1], s0[2], s0[3], kq);
        float own1 = pick4(s1[0], s1[1], s1[2], s1[3], kq);
        float own2 = pick4(s2[0], s2[1], s2[2], s2[3], kq);
        float own3 = pick4(s3[0], s3[1], s3[2], s3[3], kq);
        // foreign rows -> ONE float4 STS each into slab (r-kq)&3 (3 STS.128)
        #pragma unroll
        for (int r = 0; r < ROWS; ++r) {
            int d = (r - kq) & 3;
            if (d != 0)
                s->red[d][r][g0] = make_float4(s0[r], s1[r], s2[r], s3[r]);
        }
        if (tid < 128 && st + 1 < Tt)
            reinterpret_cast<float*>(&s->hx[64 + (xf >> 1)][xr])[xf & 1] = xnext;

        // partial exchange is closed within the g0-block group (128 threads)
        bar_named(1 + grp, 128);

        // ---- update (row kq, col g0): own regs + 3 packed slabs + bias ----
        {
            float4 p1 = s->red[1][kq][g0];
            float4 p2 = s->red[2][kq][g0];
            float4 p3 = s->red[3][kq][g0];
            float iv = own0 + cb[0] + p1.x + p2.x + p3.x;
            float fv = own1 + cb[1] + p1.y + p2.y + p3.y;
            float gv = own2 + cb[2] + p1.z + p2.z + p3.z;
            float ov = own3 + cb[3] + p1.w + p2.w + p3.w;
            float c = sig_hw(fv) * c_ + sig_hw(iv) * tanh_hw(gv);
            c_ = c;
            float h = sig_hw(ov) * tanh_hw(c);
            reinterpret_cast<float*>(&s->hx[g0 >> 1][kq])[g0 & 1] = h;
        }
        __syncthreads();   // h-ready (full CTA; also orders x STS for next GEMM)
    }

    // ---- FC head on final h ----
    if (tid < ROWS * Ll) {
        int r = tid / Ll, l = tid - r * Ll;
        float acc = b_fc[l];
        const float* wl = W_fc + l * Hh;
        #pragma unroll 16
        for (int k = 0; k < Hh; ++k)
            acc += reinterpret_cast<const float*>(&s->hx[k >> 1][r])[k & 1] * wl[k];
        out[(row0 + r) * Ll + l] = acc;
    }
}

// ---------------- host launch ----------------
extern "C" void kernel_launch(void* const* d_in, const int* in_sizes, int n_in,
                              void* d_out, int out_size) {
    const float* x    = (const float*)d_in[0];
    const float* W_ih = (const float*)d_in[1];
    const float* W_hh = (const float*)d_in[2];
    const float* b_ih = (const float*)d_in[3];
    const float* b_hh = (const float*)d_in[4];
    const float* W_fc = (const float*)d_in[5];
    const float* b_fc = (const float*)d_in[6];
    float* out = (float*)d_out;

    const size_t smem = sizeof(Smem);
    cudaFuncSetAttribute(lstm_kernel, cudaFuncAttributeMaxDynamicSharedMemorySize, (int)smem);
    lstm_kernel<<<Bb / ROWS, NTHREADS, smem>>>(x, W_ih, W_hh, b_ih, b_hh, W_fc, b_fc, out);
}